// round 5
// baseline (speedup 1.0000x reference)
#include <cuda_runtime.h>

// Problem constants (fixed by the reference: H=512, N=64, CH=1, L=2048)
#define HH   512
#define NST  64
#define LFFT 2048
#define NF   1024      // half-size complex IFFT length
#define NTH  256
#define LCHUNK 1024    // l-bins per cauchy block
#define NCHUNK (LFFT / LCHUNK)   // 2 blocks per head
#define JILP 4         // l-bins per thread

typedef unsigned long long ull;

// K_hat scratch: 512 heads x 2048 bins x complex64 = 8 MB (static, no allocation)
__device__ float2 g_khat[HH * LFFT];

__device__ __forceinline__ ull pack2(float a, float b) {
    ull r;
    asm("mov.b64 %0, {%1, %2};" : "=l"(r) : "f"(a), "f"(b));
    return r;
}
__device__ __forceinline__ void unpack2(ull v, float& a, float& b) {
    asm("mov.b64 {%0, %1}, %2;" : "=f"(a), "=f"(b) : "l"(v));
}
__device__ __forceinline__ ull ffma2(ull a, ull b, ull c) {
    ull d;
    asm("fma.rn.f32x2 %0, %1, %2, %3;" : "=l"(d) : "l"(a), "l"(b), "l"(c));
    return d;
}
__device__ __forceinline__ float frcp(float x) {
    float r;
    asm("rcp.approx.f32 %0, %1;" : "=f"(r) : "f"(x));
    return r;
}

// ============================================================================
// Kernel 1: Cauchy + Woodbury -> K_hat.
// grid = HH * NCHUNK, block = 256, each thread owns JILP=4 bins:
//   l = chunk*1024 + j*256 + tid
// ============================================================================
__global__ void __launch_bounds__(NTH, 2)
cauchy_kernel(const float* __restrict__ lam_re_in, const float* __restrict__ lam_im_in,
              const float* __restrict__ p_re,  const float* __restrict__ p_im,
              const float* __restrict__ b_re,  const float* __restrict__ b_im,
              const float* __restrict__ c_re,  const float* __restrict__ c_im,
              const float* __restrict__ log_dt)
{
    // Pre-packed f32x2 operand quads per n (64B):
    //   [0] = { (ur*dr, ui),  (ui*dr, -ur) }    u = conj(P)*B
    //   [1] = { (wr*dr, wi),  (wi*dr, -wr) }    w = conj(C)*B
    //   [2] = { (xr*dr, xi),  (xi*dr, -xr) }    x = conj(C)*P
    //   [3] = { (v*dr, -v),   (dr2, lam_im) }   v = |P|^2
    __shared__ ulonglong2 cst[NST * 4];
    __shared__ float4 rA[NST];      // raw (lam_re, ur, ui, v)  for l==1024 fixup
    __shared__ float4 rB[NST];      // raw (wr, wi, xr, xi)

    const int h     = blockIdx.x / NCHUNK;
    const int chunk = blockIdx.x % NCHUNK;
    const int tid   = threadIdx.x;
    const int lbase = chunk * LCHUNK;

    if (tid < NST) {
        const int idx = h * NST + tid;
        float lr = -log1pf(expf(lam_re_in[idx]));   // Lambda_re = -softplus
        float li = lam_im_in[idx];
        float pr = p_re[idx], pi = p_im[idx];
        float br = b_re[idx], bi = b_im[idx];
        float cr = c_re[idx], ci = c_im[idx];
        float ur = pr * br + pi * bi;
        float ui = pr * bi - pi * br;
        float v  = pr * pr + pi * pi;
        float wr = cr * br + ci * bi;
        float wi = cr * bi - ci * br;
        float xr = cr * pr + ci * pi;
        float xi = cr * pi - ci * pr;
        float dr = -lr;                 // g purely imaginary -> dr l-invariant
        cst[tid * 4 + 0] = make_ulonglong2(pack2(ur * dr, ui), pack2(ui * dr, -ur));
        cst[tid * 4 + 1] = make_ulonglong2(pack2(wr * dr, wi), pack2(wi * dr, -wr));
        cst[tid * 4 + 2] = make_ulonglong2(pack2(xr * dr, xi), pack2(xi * dr, -xr));
        cst[tid * 4 + 3] = make_ulonglong2(pack2(v * dr, -v),  pack2(dr * dr, li));
        rA[tid] = make_float4(lr, ur, ui, v);
        rB[tid] = make_float4(wr, wi, xr, xi);
    }
    const float tdt = 2.0f * expf(-log_dt[h]);    // 2/dt
    __syncthreads();

    float gi[JILP], tau[JILP];
#pragma unroll
    for (int j = 0; j < JILP; j++) {
        const int l = lbase + j * NTH + tid;
        float sp, cp;
        sincospif(l * (1.0f / 2048.0f), &sp, &cp);   // theta/2 = pi*l/2048
        tau[j] = __fdividef(sp, cp);                 // tan(theta/2)
        gi[j]  = tdt * tau[j];                       // g = i*gi
    }
    ull aU1[JILP], aU2[JILP], aW1[JILP], aW2[JILP], aX1[JILP], aX2[JILP], aV[JILP];
#pragma unroll
    for (int j = 0; j < JILP; j++) {
        aU1[j] = aU2[j] = aW1[j] = aW2[j] = aX1[j] = aX2[j] = aV[j] = 0ull;
    }
#pragma unroll 4
    for (int n = 0; n < NST; n++) {
        const ulonglong2 t0 = cst[4 * n + 0];
        const ulonglong2 t1 = cst[4 * n + 1];
        const ulonglong2 t2 = cst[4 * n + 2];
        const ulonglong2 t3 = cst[4 * n + 3];
        float dr2, lam;
        unpack2(t3.y, dr2, lam);
#pragma unroll
        for (int j = 0; j < JILP; j++) {
            const float di = gi[j] - lam;
            float2 sd;
            sd.x = frcp(fmaf(di, di, dr2));
            sd.y = di * sd.x;
            const ull q = pack2(sd.x, sd.y);
            aU1[j] = ffma2(t0.x, q, aU1[j]);
            aU2[j] = ffma2(t0.y, q, aU2[j]);
            aW1[j] = ffma2(t1.x, q, aW1[j]);
            aW2[j] = ffma2(t1.y, q, aW2[j]);
            aX1[j] = ffma2(t2.x, q, aX1[j]);
            aX2[j] = ffma2(t2.y, q, aX2[j]);
            aV[j]  = ffma2(t3.x, q, aV[j]);
        }
    }
#pragma unroll
    for (int j = 0; j < JILP; j++) {
        float x0, y0;
        unpack2(aU1[j], x0, y0); const float PRBr = x0 + y0;
        unpack2(aU2[j], x0, y0); const float PRBi = x0 + y0;
        unpack2(aW1[j], x0, y0); const float CRBr = x0 + y0;
        unpack2(aW2[j], x0, y0); const float CRBi = x0 + y0;
        unpack2(aX1[j], x0, y0); const float CRPr = x0 + y0;
        unpack2(aX2[j], x0, y0); const float CRPi = x0 + y0;
        float PRPr, PRPi;
        unpack2(aV[j], PRPr, PRPi);
        const float wr_ = 1.0f + PRPr, wi_ = PRPi;
        const float invW = frcp(fmaf(wr_, wr_, wi_ * wi_));
        const float fr = (PRBr * wr_ + PRBi * wi_) * invW;
        const float fi = (PRBi * wr_ - PRBr * wi_) * invW;
        const float er = CRBr - (CRPr * fr - CRPi * fi);
        const float ei = CRBi - (CRPr * fi + CRPi * fr);
        const int l = lbase + j * NTH + tid;
        // K_hat = (1 + i*tau) * e
        g_khat[h * LFFT + l] = make_float2(er - tau[j] * ei, ei + tau[j] * er);
    }

    // l == 1024 fixup (z = -1, eps-clamped bin) — chunk 1, j=0, tid=0 owns it.
    // Same thread wrote the NaN bin above, so this overwrite is ordered.
    if (chunk == 1 && tid == 0) {
        const float EPS = 1.1920929e-7f;
        const float gr = tdt * (2.0f / EPS);   // g real
        float PRBr = 0.f, PRBi = 0.f, PRPr = 0.f, PRPi = 0.f;
        float CRBr = 0.f, CRBi = 0.f, CRPr = 0.f, CRPi = 0.f;
        for (int n = 0; n < NST; n++) {
            const float4 a = rA[n];
            const float4 b = rB[n];
            float dr2_, lim;
            unpack2(cst[4 * n + 3].y, dr2_, lim);
            const float dr = gr - a.x;
            const float di = -lim;
            const float rinv = 1.0f / fmaf(dr, dr, di * di);
            const float Rr =  dr * rinv;
            const float Ri = -di * rinv;
            PRBr = fmaf(a.y, Rr, PRBr); PRBr = fmaf(-a.z, Ri, PRBr);
            PRBi = fmaf(a.y, Ri, PRBi); PRBi = fmaf( a.z, Rr, PRBi);
            PRPr = fmaf(a.w, Rr, PRPr);
            PRPi = fmaf(a.w, Ri, PRPi);
            CRBr = fmaf(b.x, Rr, CRBr); CRBr = fmaf(-b.y, Ri, CRBr);
            CRBi = fmaf(b.x, Ri, CRBi); CRBi = fmaf( b.y, Rr, CRBi);
            CRPr = fmaf(b.z, Rr, CRPr); CRPr = fmaf(-b.w, Ri, CRPr);
            CRPi = fmaf(b.z, Ri, CRPi); CRPi = fmaf( b.w, Rr, CRPi);
        }
        const float wr_ = 1.0f + PRPr, wi_ = PRPi;
        const float invW = 1.0f / fmaf(wr_, wr_, wi_ * wi_);
        const float fr = (PRBr * wr_ + PRBi * wi_) * invW;
        const float fi = (PRBi * wr_ - PRBr * wi_) * invW;
        const float er = CRBr - (CRPr * fr - CRPi * fi);
        const float ei = CRBi - (CRPr * fi + CRPi * fr);
        const float t2 = 2.0f / EPS;
        g_khat[h * LFFT + 1024] = make_float2(t2 * er, t2 * ei);
    }
}

// ============================================================================
// Kernel 2: Hermitian fold + 1024-pt C2R inverse FFT + store.  grid = HH.
// ============================================================================
__global__ void __launch_bounds__(NTH)
fft_kernel(const float* __restrict__ d_in, float* __restrict__ out, int write_d)
{
    __shared__ float2 Kh[LFFT];     // loaded spectrum; reused as FFT pong
    __shared__ float2 Cb[NF];       // folded C2R spectrum / FFT ping
    __shared__ float2 tw[NF / 2];   // IFFT-1024 twiddles e^{+2*pi*i*j/1024}

    const int h   = blockIdx.x;
    const int tid = threadIdx.x;

    // vectorized spectrum load (1024 float4s, 4 iters, high MLP)
    {
        const float4* src = (const float4*)(g_khat + h * LFFT);
        float4* dst = (float4*)Kh;
#pragma unroll
        for (int t = 0; t < LFFT / 2 / NTH; t++)
            dst[t * NTH + tid] = src[t * NTH + tid];
    }
    for (int j = tid; j < NF / 2; j += NTH) {
        float s, c;
        sincospif(j * (1.0f / 512.0f), &s, &c);
        tw[j] = make_float2(c, s);
    }
    __syncthreads();

    // Fold: Re(ifft2048(X)) == ifft1024(C) interleaved as (x[2n], x[2n+1])
    for (int k = tid; k < NF; k += NTH) {
        const float2 P  = Kh[k];
        const float2 Qv = Kh[(2048 - k) & 2047];
        const float2 Rv = Kh[1024 - k];
        const float2 Sv = Kh[1024 + k];
        const float Er = (P.x + Qv.x + Rv.x + Sv.x) * 0.25f;
        const float Ei = (P.y - Qv.y - Rv.y + Sv.y) * 0.25f;
        const float Dr = (P.x + Qv.x - Rv.x - Sv.x) * 0.25f;
        const float Di = (P.y - Qv.y + Rv.y - Sv.y) * 0.25f;
        float st, ct;
        sincospif(k * (1.0f / 1024.0f), &st, &ct);
        const float Or = -st * Dr - ct * Di;
        const float Oi =  ct * Dr - st * Di;
        Cb[k] = make_float2(Er + Or, Ei + Oi);
    }

    // 1024-point Stockham radix-2 inverse FFT
    {
        float2* Abuf = Cb;
        float2* Bbuf = Kh;
        int s = 1;
        for (int ncur = NF; ncur >= 4; ncur >>= 1, s <<= 1) {   // 9 stages
            __syncthreads();
#pragma unroll 2
            for (int kk = 0; kk < 2; kk++) {
                const int bi    = tid + kk * NTH;        // [0, 512)
                const int pbase = bi & ~(s - 1);
                const float2 a = Abuf[bi];
                const float2 b = Abuf[bi + NF / 2];
                const float2 w = tw[pbase];
                const int o = bi + pbase;
                Bbuf[o] = make_float2(a.x + b.x, a.y + b.y);
                const float sr = a.x - b.x, si = a.y - b.y;
                Bbuf[o + s] = make_float2(sr * w.x - si * w.y, sr * w.y + si * w.x);
            }
            float2* tmp = Abuf; Abuf = Bbuf; Bbuf = tmp;
        }
        __syncthreads();
#pragma unroll 2
        for (int kk = 0; kk < 2; kk++) {
            const int bi = tid + kk * NTH;
            const float2 a = Abuf[bi];
            const float2 b = Abuf[bi + NF / 2];
            Abuf[bi]          = make_float2(a.x + b.x, a.y + b.y);
            Abuf[bi + NF / 2] = make_float2(a.x - b.x, a.y - b.y);
        }
        __syncthreads();

        const float sc = 1.0f / (float)NF;
        float2* o2 = (float2*)out;
        for (int n2 = tid; n2 < NF; n2 += NTH) {
            const float2 cv = Abuf[n2];
            o2[h * NF + n2] = make_float2(cv.x * sc, cv.y * sc);
        }
    }

    if (write_d && tid == 0)
        out[HH * LFFT + h] = d_in[h];
}

extern "C" void kernel_launch(void* const* d_in, const int* in_sizes, int n_in,
                              void* d_out, int out_size)
{
    const float* lam_re = (const float*)d_in[0];
    const float* lam_im = (const float*)d_in[1];
    const float* p_re   = (const float*)d_in[2];
    const float* p_im   = (const float*)d_in[3];
    const float* b_re   = (const float*)d_in[4];
    const float* b_im   = (const float*)d_in[5];
    const float* c_re   = (const float*)d_in[6];
    const float* c_im   = (const float*)d_in[7];
    const float* Dv     = (const float*)d_in[8];
    const float* log_dt = (const float*)d_in[9];
    float* out = (float*)d_out;

    const int write_d = (out_size >= HH * LFFT + HH) ? 1 : 0;

    cauchy_kernel<<<HH * NCHUNK, NTH>>>(lam_re, lam_im, p_re, p_im,
                                        b_re, b_im, c_re, c_im, log_dt);
    fft_kernel<<<HH, NTH>>>(Dv, out, write_d);
}

// round 6
// speedup vs baseline: 1.1410x; 1.1410x over previous
#include <cuda_runtime.h>

// Problem constants (fixed by the reference: H=512, N=64, CH=1, L=2048)
#define HH   512
#define NST  64
#define LFFT 2048
#define NF   1024      // half-size complex IFFT length
#define NTH  256
#define LCHUNK 1024    // l-bins per cauchy block
#define NCHUNK (LFFT / LCHUNK)   // 2 blocks per head
#define JILP 4         // l-bins per thread

typedef unsigned long long ull;

// K_hat scratch: 512 heads x 2048 bins x complex64 = 8 MB (static, no allocation)
__device__ float2 g_khat[HH * LFFT];

__device__ __forceinline__ ull pack2(float a, float b) {
    ull r;
    asm("mov.b64 %0, {%1, %2};" : "=l"(r) : "f"(a), "f"(b));
    return r;
}
__device__ __forceinline__ void unpack2(ull v, float& a, float& b) {
    asm("mov.b64 {%0, %1}, %2;" : "=f"(a), "=f"(b) : "l"(v));
}
__device__ __forceinline__ ull ffma2(ull a, ull b, ull c) {
    ull d;
    asm("fma.rn.f32x2 %0, %1, %2, %3;" : "=l"(d) : "l"(a), "l"(b), "l"(c));
    return d;
}
__device__ __forceinline__ float frcp(float x) {
    float r;
    asm("rcp.approx.f32 %0, %1;" : "=f"(r) : "f"(x));
    return r;
}

// ============================================================================
// Kernel 1: Cauchy + Woodbury -> K_hat.
// grid = HH * NCHUNK, block = 256, each thread owns JILP=4 bins:
//   l = chunk*1024 + j*256 + tid
// Complex-native accumulation: 4 packed accumulators per bin.
//   R = (dr - i*di)*s,  s = 1/(dr^2+di^2),  dr = softplus(Lambda_re) (l-invariant)
//   acc  += (c_r*dr, c_i*dr)*(s,s) + (c_i, -c_r)*(ds,ds)    [complex sums]
//   accV += (v*dr, -v)*(s, ds)                               [PRP]
// ============================================================================
__global__ void __launch_bounds__(NTH, 3)
cauchy_kernel(const float* __restrict__ lam_re_in, const float* __restrict__ lam_im_in,
              const float* __restrict__ p_re,  const float* __restrict__ p_im,
              const float* __restrict__ b_re,  const float* __restrict__ b_im,
              const float* __restrict__ c_re,  const float* __restrict__ c_im,
              const float* __restrict__ log_dt)
{
    // Pre-packed f32x2 operand quads per n (64B):
    //   [0] = { (ur*dr, ui*dr),  (ui, -ur) }    u = conj(P)*B
    //   [1] = { (wr*dr, wi*dr),  (wi, -wr) }    w = conj(C)*B
    //   [2] = { (xr*dr, xi*dr),  (xi, -xr) }    x = conj(C)*P
    //   [3] = { (v*dr, -v),      (dr2, lam) }   v = |P|^2
    __shared__ ulonglong2 cst[NST * 4];
    __shared__ float4 rA[NST];      // raw (lam_re, ur, ui, v)  for l==1024 fixup
    __shared__ float4 rB[NST];      // raw (wr, wi, xr, xi)

    const int h     = blockIdx.x / NCHUNK;
    const int chunk = blockIdx.x % NCHUNK;
    const int tid   = threadIdx.x;
    const int lbase = chunk * LCHUNK;

    if (tid < NST) {
        const int idx = h * NST + tid;
        float lr = -log1pf(expf(lam_re_in[idx]));   // Lambda_re = -softplus
        float li = lam_im_in[idx];
        float pr = p_re[idx], pi = p_im[idx];
        float br = b_re[idx], bi = b_im[idx];
        float cr = c_re[idx], ci = c_im[idx];
        float ur = pr * br + pi * bi;
        float ui = pr * bi - pi * br;
        float v  = pr * pr + pi * pi;
        float wr = cr * br + ci * bi;
        float wi = cr * bi - ci * br;
        float xr = cr * pr + ci * pi;
        float xi = cr * pi - ci * pr;
        float dr = -lr;                 // g purely imaginary -> dr l-invariant
        cst[tid * 4 + 0] = make_ulonglong2(pack2(ur * dr, ui * dr), pack2(ui, -ur));
        cst[tid * 4 + 1] = make_ulonglong2(pack2(wr * dr, wi * dr), pack2(wi, -wr));
        cst[tid * 4 + 2] = make_ulonglong2(pack2(xr * dr, xi * dr), pack2(xi, -xr));
        cst[tid * 4 + 3] = make_ulonglong2(pack2(v * dr, -v),       pack2(dr * dr, li));
        rA[tid] = make_float4(lr, ur, ui, v);
        rB[tid] = make_float4(wr, wi, xr, xi);
    }
    const float tdt = 2.0f * expf(-log_dt[h]);    // 2/dt
    __syncthreads();

    float gi[JILP], tau[JILP];
#pragma unroll
    for (int j = 0; j < JILP; j++) {
        const int l = lbase + j * NTH + tid;
        float sp, cp;
        sincospif(l * (1.0f / 2048.0f), &sp, &cp);   // theta/2 = pi*l/2048
        tau[j] = __fdividef(sp, cp);                 // tan(theta/2)
        gi[j]  = tdt * tau[j];                       // g = i*gi
    }
    ull aU[JILP], aW[JILP], aX[JILP], aV[JILP];
#pragma unroll
    for (int j = 0; j < JILP; j++)
        aU[j] = aW[j] = aX[j] = aV[j] = 0ull;

#pragma unroll 4
    for (int n = 0; n < NST; n++) {
        const ulonglong2 t0 = cst[4 * n + 0];
        const ulonglong2 t1 = cst[4 * n + 1];
        const ulonglong2 t2 = cst[4 * n + 2];
        const ulonglong2 t3 = cst[4 * n + 3];
        float dr2, lam;
        unpack2(t3.y, dr2, lam);
#pragma unroll
        for (int j = 0; j < JILP; j++) {
            const float di = gi[j] - lam;
            const float s  = frcp(fmaf(di, di, dr2));
            const float ds = di * s;
            const ull s2  = pack2(s, s);
            const ull ds2 = pack2(ds, ds);
            const ull q   = pack2(s, ds);
            aU[j] = ffma2(t0.x, s2,  aU[j]);
            aU[j] = ffma2(t0.y, ds2, aU[j]);
            aW[j] = ffma2(t1.x, s2,  aW[j]);
            aW[j] = ffma2(t1.y, ds2, aW[j]);
            aX[j] = ffma2(t2.x, s2,  aX[j]);
            aX[j] = ffma2(t2.y, ds2, aX[j]);
            aV[j] = ffma2(t3.x, q,   aV[j]);
        }
    }
#pragma unroll
    for (int j = 0; j < JILP; j++) {
        float PRBr, PRBi, CRBr, CRBi, CRPr, CRPi, PRPr, PRPi;
        unpack2(aU[j], PRBr, PRBi);
        unpack2(aW[j], CRBr, CRBi);
        unpack2(aX[j], CRPr, CRPi);
        unpack2(aV[j], PRPr, PRPi);
        const float wr_ = 1.0f + PRPr, wi_ = PRPi;
        const float invW = frcp(fmaf(wr_, wr_, wi_ * wi_));
        const float fr = (PRBr * wr_ + PRBi * wi_) * invW;
        const float fi = (PRBi * wr_ - PRBr * wi_) * invW;
        const float er = CRBr - (CRPr * fr - CRPi * fi);
        const float ei = CRBi - (CRPr * fi + CRPi * fr);
        const int l = lbase + j * NTH + tid;
        // K_hat = (1 + i*tau) * e
        g_khat[h * LFFT + l] = make_float2(er - tau[j] * ei, ei + tau[j] * er);
    }

    // l == 1024 fixup (z = -1, eps-clamped bin) — chunk 1, tid 0 wrote the NaN
    // bin above (j=0), so this overwrite is same-thread ordered.
    if (chunk == 1 && tid == 0) {
        const float EPS = 1.1920929e-7f;
        const float gr = tdt * (2.0f / EPS);   // g real
        float PRBr = 0.f, PRBi = 0.f, PRPr = 0.f, PRPi = 0.f;
        float CRBr = 0.f, CRBi = 0.f, CRPr = 0.f, CRPi = 0.f;
        for (int n = 0; n < NST; n++) {
            const float4 a = rA[n];
            const float4 b = rB[n];
            float dr2_, lim;
            unpack2(cst[4 * n + 3].y, dr2_, lim);
            const float dr = gr - a.x;
            const float di = -lim;
            const float rinv = 1.0f / fmaf(dr, dr, di * di);
            const float Rr =  dr * rinv;
            const float Ri = -di * rinv;
            PRBr = fmaf(a.y, Rr, PRBr); PRBr = fmaf(-a.z, Ri, PRBr);
            PRBi = fmaf(a.y, Ri, PRBi); PRBi = fmaf( a.z, Rr, PRBi);
            PRPr = fmaf(a.w, Rr, PRPr);
            PRPi = fmaf(a.w, Ri, PRPi);
            CRBr = fmaf(b.x, Rr, CRBr); CRBr = fmaf(-b.y, Ri, CRBr);
            CRBi = fmaf(b.x, Ri, CRBi); CRBi = fmaf( b.y, Rr, CRBi);
            CRPr = fmaf(b.z, Rr, CRPr); CRPr = fmaf(-b.w, Ri, CRPr);
            CRPi = fmaf(b.z, Ri, CRPi); CRPi = fmaf( b.w, Rr, CRPi);
        }
        const float wr_ = 1.0f + PRPr, wi_ = PRPi;
        const float invW = 1.0f / fmaf(wr_, wr_, wi_ * wi_);
        const float fr = (PRBr * wr_ + PRBi * wi_) * invW;
        const float fi = (PRBi * wr_ - PRBr * wi_) * invW;
        const float er = CRBr - (CRPr * fr - CRPi * fi);
        const float ei = CRBi - (CRPr * fi + CRPi * fr);
        const float t2 = 2.0f / EPS;
        g_khat[h * LFFT + 1024] = make_float2(t2 * er, t2 * ei);
    }
}

// ============================================================================
// Kernel 2: Hermitian fold + 1024-pt C2R inverse FFT + store.  grid = HH.
// ============================================================================
__global__ void __launch_bounds__(NTH)
fft_kernel(const float* __restrict__ d_in, float* __restrict__ out, int write_d)
{
    __shared__ float2 Kh[LFFT];     // loaded spectrum; reused as FFT pong
    __shared__ float2 Cb[NF];       // folded C2R spectrum / FFT ping
    __shared__ float2 tw[NF / 2];   // IFFT-1024 twiddles e^{+2*pi*i*j/1024}

    const int h   = blockIdx.x;
    const int tid = threadIdx.x;

    // vectorized spectrum load (1024 float4s, 4 iters, high MLP)
    {
        const float4* src = (const float4*)(g_khat + h * LFFT);
        float4* dst = (float4*)Kh;
#pragma unroll
        for (int t = 0; t < LFFT / 2 / NTH; t++)
            dst[t * NTH + tid] = src[t * NTH + tid];
    }
    for (int j = tid; j < NF / 2; j += NTH) {
        float s, c;
        sincospif(j * (1.0f / 512.0f), &s, &c);
        tw[j] = make_float2(c, s);
    }
    __syncthreads();

    // Fold: Re(ifft2048(X)) == ifft1024(C) interleaved as (x[2n], x[2n+1])
    for (int k = tid; k < NF; k += NTH) {
        const float2 P  = Kh[k];
        const float2 Qv = Kh[(2048 - k) & 2047];
        const float2 Rv = Kh[1024 - k];
        const float2 Sv = Kh[1024 + k];
        const float Er = (P.x + Qv.x + Rv.x + Sv.x) * 0.25f;
        const float Ei = (P.y - Qv.y - Rv.y + Sv.y) * 0.25f;
        const float Dr = (P.x + Qv.x - Rv.x - Sv.x) * 0.25f;
        const float Di = (P.y - Qv.y + Rv.y - Sv.y) * 0.25f;
        float st, ct;
        sincospif(k * (1.0f / 1024.0f), &st, &ct);
        const float Or = -st * Dr - ct * Di;
        const float Oi =  ct * Dr - st * Di;
        Cb[k] = make_float2(Er + Or, Ei + Oi);
    }

    // 1024-point Stockham radix-2 inverse FFT
    {
        float2* Abuf = Cb;
        float2* Bbuf = Kh;
        int s = 1;
        for (int ncur = NF; ncur >= 4; ncur >>= 1, s <<= 1) {   // 9 stages
            __syncthreads();
#pragma unroll 2
            for (int kk = 0; kk < 2; kk++) {
                const int bi    = tid + kk * NTH;        // [0, 512)
                const int pbase = bi & ~(s - 1);
                const float2 a = Abuf[bi];
                const float2 b = Abuf[bi + NF / 2];
                const float2 w = tw[pbase];
                const int o = bi + pbase;
                Bbuf[o] = make_float2(a.x + b.x, a.y + b.y);
                const float sr = a.x - b.x, si = a.y - b.y;
                Bbuf[o + s] = make_float2(sr * w.x - si * w.y, sr * w.y + si * w.x);
            }
            float2* tmp = Abuf; Abuf = Bbuf; Bbuf = tmp;
        }
        __syncthreads();
#pragma unroll 2
        for (int kk = 0; kk < 2; kk++) {
            const int bi = tid + kk * NTH;
            const float2 a = Abuf[bi];
            const float2 b = Abuf[bi + NF / 2];
            Abuf[bi]          = make_float2(a.x + b.x, a.y + b.y);
            Abuf[bi + NF / 2] = make_float2(a.x - b.x, a.y - b.y);
        }
        __syncthreads();

        const float sc = 1.0f / (float)NF;
        float2* o2 = (float2*)out;
        for (int n2 = tid; n2 < NF; n2 += NTH) {
            const float2 cv = Abuf[n2];
            o2[h * NF + n2] = make_float2(cv.x * sc, cv.y * sc);
        }
    }

    if (write_d && tid == 0)
        out[HH * LFFT + h] = d_in[h];
}

extern "C" void kernel_launch(void* const* d_in, const int* in_sizes, int n_in,
                              void* d_out, int out_size)
{
    const float* lam_re = (const float*)d_in[0];
    const float* lam_im = (const float*)d_in[1];
    const float* p_re   = (const float*)d_in[2];
    const float* p_im   = (const float*)d_in[3];
    const float* b_re   = (const float*)d_in[4];
    const float* b_im   = (const float*)d_in[5];
    const float* c_re   = (const float*)d_in[6];
    const float* c_im   = (const float*)d_in[7];
    const float* Dv     = (const float*)d_in[8];
    const float* log_dt = (const float*)d_in[9];
    float* out = (float*)d_out;

    const int write_d = (out_size >= HH * LFFT + HH) ? 1 : 0;

    cauchy_kernel<<<HH * NCHUNK, NTH>>>(lam_re, lam_im, p_re, p_im,
                                        b_re, b_im, c_re, c_im, log_dt);
    fft_kernel<<<HH, NTH>>>(Dv, out, write_d);
}